// round 15
// baseline (speedup 1.0000x reference)
#include <cuda_runtime.h>
#include <cuda_fp16.h>
#include <math.h>
#include <stdint.h>

// ---------------------------------------------------------------------------
// Problem dimensions
// ---------------------------------------------------------------------------
#define SQ   2048
#define HDIM 1024
#define NH   16
#define HD   64
#define ISZ  4096

// ---------------------------------------------------------------------------
// Scratch
// ---------------------------------------------------------------------------
__device__ __half g_xn [SQ * HDIM];
__device__ __half g_q  [SQ * HDIM];
__device__ __half g_k  [SQ * HDIM];
__device__ __half g_v  [SQ * HDIM];
__device__ __half g_att[SQ * HDIM];
__device__ __half g_ctx[SQ * HDIM];
__device__ float  g_h1 [SQ * HDIM];
__device__ float  g_h2 [SQ * HDIM];
__device__ __half g_gate[SQ * ISZ];
__device__ __half g_up  [SQ * ISZ];
__device__ __half g_gu  [SQ * ISZ];
// transposed fp16 weights [N][K]
__device__ __half g_wt_saq[HDIM * HDIM];
__device__ __half g_wt_sak[HDIM * HDIM];
__device__ __half g_wt_sav[HDIM * HDIM];
__device__ __half g_wt_sao[HDIM * HDIM];
__device__ __half g_wt_caq[HDIM * HDIM];
__device__ __half g_wt_cak[HDIM * HDIM];
__device__ __half g_wt_cav[HDIM * HDIM];
__device__ __half g_wt_cao[HDIM * HDIM];
__device__ __half g_wt_g  [ISZ * HDIM];
__device__ __half g_wt_u  [ISZ * HDIM];
__device__ __half g_wt_d  [HDIM * ISZ];

// ---------------------------------------------------------------------------
// Helpers
// ---------------------------------------------------------------------------
__device__ __forceinline__ void mma_f16(float* c, const uint32_t* a,
                                        uint32_t b0, uint32_t b1) {
    asm volatile(
        "mma.sync.aligned.m16n8k16.row.col.f32.f16.f16.f32 "
        "{%0,%1,%2,%3}, {%4,%5,%6,%7}, {%8,%9}, {%0,%1,%2,%3};"
        : "+f"(c[0]), "+f"(c[1]), "+f"(c[2]), "+f"(c[3])
        : "r"(a[0]), "r"(a[1]), "r"(a[2]), "r"(a[3]), "r"(b0), "r"(b1));
}

__device__ __forceinline__ void cp16(uint32_t smem_dst, const void* gsrc) {
    asm volatile("cp.async.ca.shared.global [%0], [%1], 16;\n"
                 :: "r"(smem_dst), "l"(gsrc));
}
__device__ __forceinline__ void cp_commit() {
    asm volatile("cp.async.commit_group;\n" ::: "memory");
}
template <int N>
__device__ __forceinline__ void cp_wait() {
    asm volatile("cp.async.wait_group %0;\n" :: "n"(N) : "memory");
}

__device__ __forceinline__ uint32_t h2u(half2 h) {
    return *reinterpret_cast<uint32_t*>(&h);
}

// ---------------------------------------------------------------------------
// Fused conversion kernel: 11 weight transposes + ctx fp16 convert, 1 launch.
// Regions by blockIdx.x:
//   [0, 8192):      8 HxH weights, 1024 tiles each (32x32)
//   [8192, 12288):  gate  (K=1024, N=4096)
//   [12288, 16384): up    (K=1024, N=4096)
//   [16384, 20480): down  (K=4096, N=1024)
//   [20480, 22528): context fp32->fp16 copy
// ---------------------------------------------------------------------------
struct CvtArgs {
    const float* src[12];
    __half*      dst[12];
};

#define CVT_GRID 22528

__global__ void __launch_bounds__(256) fused_cvt_kernel(CvtArgs args)
{
    const int b   = blockIdx.x;
    const int tid = threadIdx.x;

    if (b >= 20480) {
        const int i = (b - 20480) * 256 + tid;
        float4 v = ((const float4*)args.src[11])[i];
        half2* o = (half2*)args.dst[11];
        o[2 * i + 0] = __floats2half2_rn(v.x, v.y);
        o[2 * i + 1] = __floats2half2_rn(v.z, v.w);
        return;
    }

    int wi, t, K, N;
    if (b < 8192)        { wi = b >> 10; t = b & 1023;  K = HDIM; N = HDIM; }
    else if (b < 12288)  { wi = 8;  t = b - 8192;       K = HDIM; N = ISZ;  }
    else if (b < 16384)  { wi = 9;  t = b - 12288;      K = HDIM; N = ISZ;  }
    else                 { wi = 10; t = b - 16384;      K = ISZ;  N = HDIM; }

    const int ntiles_n = N >> 5;
    const int n0 = (t % ntiles_n) * 32;
    const int k0 = (t / ntiles_n) * 32;

    const float* in  = args.src[wi];
    __half*      out = args.dst[wi];

    __shared__ float tt[32][33];
    const int tx = tid & 31;
    const int ty = tid >> 5;
    #pragma unroll
    for (int j = 0; j < 4; ++j)
        tt[ty + j * 8][tx] = in[(size_t)(k0 + ty + j * 8) * N + n0 + tx];
    __syncthreads();
    #pragma unroll
    for (int j = 0; j < 4; ++j)
        out[(size_t)(n0 + ty + j * 8) * K + k0 + tx] =
            __float2half_rn(tt[tx][ty + j * 8]);
}

// ---------------------------------------------------------------------------
// RMSNorm: fp32 in -> fp16 out
// ---------------------------------------------------------------------------
__global__ void __launch_bounds__(256) rmsnorm16_kernel(
    const float* __restrict__ x, const float* __restrict__ w,
    __half* __restrict__ y)
{
    const int row = blockIdx.x;
    const int t   = threadIdx.x;
    float4 vx = ((const float4*)(x + (size_t)row * HDIM))[t];
    float s = vx.x*vx.x + vx.y*vx.y + vx.z*vx.z + vx.w*vx.w;
    #pragma unroll
    for (int o = 16; o; o >>= 1) s += __shfl_xor_sync(0xffffffffu, s, o);

    __shared__ float red[8];
    __shared__ float s_inv;
    if ((t & 31) == 0) red[t >> 5] = s;
    __syncthreads();
    if (t == 0) {
        float tot = 0.f;
        #pragma unroll
        for (int i = 0; i < 8; ++i) tot += red[i];
        s_inv = 1.0f / sqrtf(tot * (1.0f / (float)HDIM) + 1e-6f);
    }
    __syncthreads();
    const float r = s_inv;
    float4 vw = ((const float4*)w)[t];
    half2* yrow = (half2*)(y + (size_t)row * HDIM);
    yrow[2 * t + 0] = __floats2half2_rn(vx.x * r * vw.x, vx.y * r * vw.y);
    yrow[2 * t + 1] = __floats2half2_rn(vx.z * r * vw.z, vx.w * r * vw.w);
}

// ---------------------------------------------------------------------------
// fp16 mma.sync GEMM (m16n8k16), 3-stage cp.async pipeline (proven R12/R13).
// ---------------------------------------------------------------------------
#define RS16  20
#define A16_STG (128 * RS16)
#define B16_STG (64 * RS16)
#define GEMM_SMEM ((3 * A16_STG + 3 * B16_STG) * 4)

template <int OUTF16>
__global__ void __launch_bounds__(256, 2) gemm_f16_kernel(
    const __half* __restrict__ A,
    const __half* __restrict__ B0, const __half* __restrict__ B1,
    const __half* __restrict__ B2,
    const float* __restrict__ R,
    void* __restrict__ C0, void* __restrict__ C1, void* __restrict__ C2,
    int M, int N, int K)
{
    extern __shared__ uint32_t smw[];
    uint32_t* As = smw;
    uint32_t* Bs = smw + 3 * A16_STG;

    const __half* B = (blockIdx.z == 0) ? B0 : (blockIdx.z == 1 ? B1 : B2);
    void*         C = (blockIdx.z == 0) ? C0 : (blockIdx.z == 1 ? C1 : C2);

    const int tid  = threadIdx.x;
    const int lane = tid & 31;
    const int wid  = tid >> 5;
    const int g    = lane >> 2;
    const int tig  = lane & 3;
    const int wm   = (wid >> 1) * 32;
    const int wn   = (wid & 1) * 32;
    const int bm   = blockIdx.y * 128;
    const int bn   = blockIdx.x * 64;

    float acc[2][4][4];
    #pragma unroll
    for (int mt = 0; mt < 2; ++mt)
        #pragma unroll
        for (int nt = 0; nt < 4; ++nt)
            #pragma unroll
            for (int e = 0; e < 4; ++e) acc[mt][nt][e] = 0.f;

    const int niter = K >> 5;

    auto issue = [&](int i, int s) {
        const int k0 = i << 5;
        #pragma unroll
        for (int it = 0; it < 2; ++it) {
            const int chunk = tid + it * 256;
            const int r = chunk >> 2;
            const int c = chunk & 3;
            uint32_t dst = (uint32_t)__cvta_generic_to_shared(
                &As[s * A16_STG + r * RS16 + 4 * c]);
            cp16(dst, A + (size_t)(bm + r) * K + k0 + 8 * c);
        }
        {
            const int r = tid >> 2;
            const int c = tid & 3;
            uint32_t dst = (uint32_t)__cvta_generic_to_shared(
                &Bs[s * B16_STG + r * RS16 + 4 * c]);
            cp16(dst, B + (size_t)(bn + r) * K + k0 + 8 * c);
        }
    };

    issue(0, 0);
    cp_commit();
    if (niter > 1) issue(1, 1);
    cp_commit();

    for (int i = 0; i < niter; ++i) {
        const int s = i - (i / 3) * 3;
        cp_wait<1>();
        __syncthreads();

        const uint32_t* Ast = As + s * A16_STG;
        const uint32_t* Bst = Bs + s * B16_STG;

        uint32_t af[2][2][4];
        uint32_t bf[2][4][2];
        #pragma unroll
        for (int kt = 0; kt < 2; ++kt) {
            #pragma unroll
            for (int nt = 0; nt < 4; ++nt) {
                const int base = (wn + nt * 8 + g) * RS16 + kt * 8 + tig;
                bf[kt][nt][0] = Bst[base];
                bf[kt][nt][1] = Bst[base + 4];
            }
            #pragma unroll
            for (int mt = 0; mt < 2; ++mt) {
                const int b0 = (wm + mt * 16 + g) * RS16 + kt * 8 + tig;
                af[kt][mt][0] = Ast[b0];
                af[kt][mt][1] = Ast[b0 + 8 * RS16];
                af[kt][mt][2] = Ast[b0 + 4];
                af[kt][mt][3] = Ast[b0 + 8 * RS16 + 4];
            }
        }

        #pragma unroll
        for (int kt = 0; kt < 2; ++kt)
            #pragma unroll
            for (int mt = 0; mt < 2; ++mt)
                #pragma unroll
                for (int nt = 0; nt < 4; ++nt)
                    mma_f16(acc[mt][nt], af[kt][mt],
                            bf[kt][nt][0], bf[kt][nt][1]);

        __syncthreads();
        const int j = i + 2;
        if (j < niter) issue(j, j - (j / 3) * 3);
        cp_commit();
    }

    #pragma unroll
    for (int mt = 0; mt < 2; ++mt) {
        const int r0 = bm + wm + mt * 16 + g;
        const int r1 = r0 + 8;
        #pragma unroll
        for (int nt = 0; nt < 4; ++nt) {
            const int col = bn + wn + nt * 8 + 2 * tig;
            if (OUTF16) {
                __half* Ch = (__half*)C;
                *(half2*)(Ch + (size_t)r0 * N + col) =
                    __floats2half2_rn(acc[mt][nt][0], acc[mt][nt][1]);
                *(half2*)(Ch + (size_t)r1 * N + col) =
                    __floats2half2_rn(acc[mt][nt][2], acc[mt][nt][3]);
            } else {
                float* Cf = (float*)C;
                float2 v0 = make_float2(acc[mt][nt][0], acc[mt][nt][1]);
                float2 v1 = make_float2(acc[mt][nt][2], acc[mt][nt][3]);
                if (R) {
                    float2 a0 = *(const float2*)(R + (size_t)r0 * N + col);
                    float2 a1 = *(const float2*)(R + (size_t)r1 * N + col);
                    v0.x += a0.x; v0.y += a0.y;
                    v1.x += a1.x; v1.y += a1.y;
                }
                *(float2*)(Cf + (size_t)r0 * N + col) = v0;
                *(float2*)(Cf + (size_t)r1 * N + col) = v1;
            }
        }
    }
}

// ---------------------------------------------------------------------------
// Flash attention, fp16 mma core (R13, proven).
// ---------------------------------------------------------------------------
#define AS16 36
#define ATT_SMEM ((128 * AS16 + 64 * AS16 + 64 * AS16) * 4)

__global__ void __launch_bounds__(256) attn_f16_kernel(
    const __half* __restrict__ Qg, const __half* __restrict__ Kg,
    const __half* __restrict__ Vg, __half* __restrict__ Og)
{
    extern __shared__ uint32_t sm[];
    uint32_t* Qs = sm;
    uint32_t* Ks = sm + 128 * AS16;
    uint32_t* Vt = sm + 192 * AS16;

    const int tid  = threadIdx.x;
    const int lane = tid & 31;
    const int wid  = tid >> 5;
    const int g    = lane >> 2;
    const int tig  = lane & 3;
    const int i0   = blockIdx.x * 128;
    const int hoff = blockIdx.y * HD;
    const int qrow = wid * 16;

    #pragma unroll
    for (int it = 0; it < 4; ++it) {
        const int chunk = tid + it * 256;
        const int r = chunk >> 3;
        const int c = chunk & 7;
        uint32_t dst = (uint32_t)__cvta_generic_to_shared(&Qs[r * AS16 + 4 * c]);
        cp16(dst, Qg + (size_t)(i0 + r) * HDIM + hoff + 8 * c);
    }
    cp_commit();

    float m0 = -1e30f, m1 = -1e30f;
    float l0 = 0.f, l1 = 0.f;
    float o[8][4];
    #pragma unroll
    for (int nt = 0; nt < 8; ++nt)
        #pragma unroll
        for (int e = 0; e < 4; ++e) o[nt][e] = 0.f;

    for (int j0 = 0; j0 < SQ; j0 += 64) {
        __syncthreads();
        #pragma unroll
        for (int it = 0; it < 2; ++it) {
            const int chunk = tid + it * 256;
            const int r = chunk >> 3;
            const int c = chunk & 7;
            uint32_t dst = (uint32_t)__cvta_generic_to_shared(
                &Ks[r * AS16 + 4 * c]);
            cp16(dst, Kg + (size_t)(j0 + r) * HDIM + hoff + 8 * c);
        }
        cp_commit();
        __half* Vth = (__half*)Vt;
        #pragma unroll
        for (int it = 0; it < 4; ++it) {
            const int r  = it * 16 + (tid >> 4);
            const int c4 = (tid & 15) << 2;
            const __half* vp = Vg + (size_t)(j0 + r) * HDIM + hoff + c4;
            half2 v0 = *(const half2*)(vp);
            half2 v1 = *(const half2*)(vp + 2);
            Vth[((c4 + 0) * AS16 + (r >> 1)) * 2 + (r & 1)] = __low2half(v0);
            Vth[((c4 + 1) * AS16 + (r >> 1)) * 2 + (r & 1)] = __high2half(v0);
            Vth[((c4 + 2) * AS16 + (r >> 1)) * 2 + (r & 1)] = __low2half(v1);
            Vth[((c4 + 3) * AS16 + (r >> 1)) * 2 + (r & 1)] = __high2half(v1);
        }
        cp_wait<0>();
        __syncthreads();

        float s[8][4];
        #pragma unroll
        for (int nt = 0; nt < 8; ++nt)
            #pragma unroll
            for (int e = 0; e < 4; ++e) s[nt][e] = 0.f;

        #pragma unroll
        for (int kt = 0; kt < 4; ++kt) {
            uint32_t a[4];
            const int base = (qrow + g) * AS16 + kt * 8 + tig;
            a[0] = Qs[base];
            a[1] = Qs[base + 8 * AS16];
            a[2] = Qs[base + 4];
            a[3] = Qs[base + 8 * AS16 + 4];
            #pragma unroll
            for (int nt = 0; nt < 8; ++nt) {
                const int jb = (nt * 8 + g) * AS16 + kt * 8 + tig;
                mma_f16(s[nt], a, Ks[jb], Ks[jb + 4]);
            }
        }
        #pragma unroll
        for (int nt = 0; nt < 8; ++nt)
            #pragma unroll
            for (int e = 0; e < 4; ++e) s[nt][e] *= 0.125f;

        float mt0 = -1e30f, mt1 = -1e30f;
        #pragma unroll
        for (int nt = 0; nt < 8; ++nt) {
            mt0 = fmaxf(mt0, fmaxf(s[nt][0], s[nt][1]));
            mt1 = fmaxf(mt1, fmaxf(s[nt][2], s[nt][3]));
        }
        mt0 = fmaxf(mt0, __shfl_xor_sync(0xffffffffu, mt0, 1));
        mt0 = fmaxf(mt0, __shfl_xor_sync(0xffffffffu, mt0, 2));
        mt1 = fmaxf(mt1, __shfl_xor_sync(0xffffffffu, mt1, 1));
        mt1 = fmaxf(mt1, __shfl_xor_sync(0xffffffffu, mt1, 2));

        const float mn0 = fmaxf(m0, mt0);
        const float mn1 = fmaxf(m1, mt1);
        const float c0 = __expf(m0 - mn0);
        const float c1 = __expf(m1 - mn1);
        m0 = mn0; m1 = mn1;

        float ps0 = 0.f, ps1 = 0.f;
        #pragma unroll
        for (int nt = 0; nt < 8; ++nt) {
            s[nt][0] = __expf(s[nt][0] - mn0);
            s[nt][1] = __expf(s[nt][1] - mn0);
            s[nt][2] = __expf(s[nt][2] - mn1);
            s[nt][3] = __expf(s[nt][3] - mn1);
            ps0 += s[nt][0] + s[nt][1];
            ps1 += s[nt][2] + s[nt][3];
        }
        ps0 += __shfl_xor_sync(0xffffffffu, ps0, 1);
        ps0 += __shfl_xor_sync(0xffffffffu, ps0, 2);
        ps1 += __shfl_xor_sync(0xffffffffu, ps1, 1);
        ps1 += __shfl_xor_sync(0xffffffffu, ps1, 2);
        l0 = l0 * c0 + ps0;
        l1 = l1 * c1 + ps1;

        #pragma unroll
        for (int nt = 0; nt < 8; ++nt) {
            o[nt][0] *= c0; o[nt][1] *= c0;
            o[nt][2] *= c1; o[nt][3] *= c1;
        }

        #pragma unroll
        for (int jt = 0; jt < 4; ++jt) {
            uint32_t a[4];
            a[0] = h2u(__floats2half2_rn(s[2 * jt][0],     s[2 * jt][1]));
            a[1] = h2u(__floats2half2_rn(s[2 * jt][2],     s[2 * jt][3]));
            a[2] = h2u(__floats2half2_rn(s[2 * jt + 1][0], s[2 * jt + 1][1]));
            a[3] = h2u(__floats2half2_rn(s[2 * jt + 1][2], s[2 * jt + 1][3]));
            #pragma unroll
            for (int nt = 0; nt < 8; ++nt) {
                const int vb = (nt * 8 + g) * AS16 + jt * 8 + tig;
                mma_f16(o[nt], a, Vt[vb], Vt[vb + 4]);
            }
        }
    }

    const float i0f = 1.0f / l0;
    const float i1f = 1.0f / l1;
    const int r0 = i0 + qrow + g;
    const int r1 = r0 + 8;
    #pragma unroll
    for (int nt = 0; nt < 8; ++nt) {
        const int col = hoff + nt * 8 + 2 * tig;
        *(half2*)(Og + (size_t)r0 * HDIM + col) =
            __floats2half2_rn(o[nt][0] * i0f, o[nt][1] * i0f);
        *(half2*)(Og + (size_t)r1 * HDIM + col) =
            __floats2half2_rn(o[nt][2] * i1f, o[nt][3] * i1f);
    }
}

// ---------------------------------------------------------------------------
// SwiGLU elementwise: fp16 in/out
// ---------------------------------------------------------------------------
__global__ void __launch_bounds__(256) silu16_kernel(
    const __half* __restrict__ g, const __half* __restrict__ u,
    __half* __restrict__ out, int n2)
{
    const int i = blockIdx.x * blockDim.x + threadIdx.x;
    if (i >= n2) return;
    float2 gf = __half22float2(((const half2*)g)[i]);
    float2 uf = __half22float2(((const half2*)u)[i]);
    float ox = gf.x * (1.0f / (1.0f + __expf(-gf.x))) * uf.x;
    float oy = gf.y * (1.0f / (1.0f + __expf(-gf.y))) * uf.y;
    ((half2*)out)[i] = __floats2half2_rn(ox, oy);
}

// ---------------------------------------------------------------------------
// Launch sequence
// ---------------------------------------------------------------------------
extern "C" void kernel_launch(void* const* d_in, const int* in_sizes, int n_in,
                              void* d_out, int out_size)
{
    (void)in_sizes; (void)n_in; (void)out_size;

    const float* hidden   = (const float*)d_in[0];
    const float* context  = (const float*)d_in[1];
    const float* sa_norm  = (const float*)d_in[2];
    const float* sa_wq    = (const float*)d_in[3];
    const float* sa_wk    = (const float*)d_in[4];
    const float* sa_wv    = (const float*)d_in[5];
    const float* sa_wo    = (const float*)d_in[6];
    const float* ca_norm  = (const float*)d_in[7];
    const float* ca_wq    = (const float*)d_in[8];
    const float* ca_wk    = (const float*)d_in[9];
    const float* ca_wv    = (const float*)d_in[10];
    const float* ca_wo    = (const float*)d_in[11];
    const float* mlp_norm = (const float*)d_in[12];
    const float* w_gate   = (const float*)d_in[13];
    const float* w_up     = (const float*)d_in[14];
    const float* w_down   = (const float*)d_in[15];
    float* out = (float*)d_out;

    __half *xn, *q, *k, *v, *att, *ctx16, *gate, *up, *gu;
    float *h1, *h2;
    cudaGetSymbolAddress((void**)&xn,    g_xn);
    cudaGetSymbolAddress((void**)&q,     g_q);
    cudaGetSymbolAddress((void**)&k,     g_k);
    cudaGetSymbolAddress((void**)&v,     g_v);
    cudaGetSymbolAddress((void**)&att,   g_att);
    cudaGetSymbolAddress((void**)&ctx16, g_ctx);
    cudaGetSymbolAddress((void**)&h1,    g_h1);
    cudaGetSymbolAddress((void**)&h2,    g_h2);
    cudaGetSymbolAddress((void**)&gate,  g_gate);
    cudaGetSymbolAddress((void**)&up,    g_up);
    cudaGetSymbolAddress((void**)&gu,    g_gu);

    __half *wsaq, *wsak, *wsav, *wsao, *wcaq, *wcak, *wcav, *wcao, *wg, *wu, *wd;
    cudaGetSymbolAddress((void**)&wsaq, g_wt_saq);
    cudaGetSymbolAddress((void**)&wsak, g_wt_sak);
    cudaGetSymbolAddress((void**)&wsav, g_wt_sav);
    cudaGetSymbolAddress((void**)&wsao, g_wt_sao);
    cudaGetSymbolAddress((void**)&wcaq, g_wt_caq);
    cudaGetSymbolAddress((void**)&wcak, g_wt_cak);
    cudaGetSymbolAddress((void**)&wcav, g_wt_cav);
    cudaGetSymbolAddress((void**)&wcao, g_wt_cao);
    cudaGetSymbolAddress((void**)&wg,   g_wt_g);
    cudaGetSymbolAddress((void**)&wu,   g_wt_u);
    cudaGetSymbolAddress((void**)&wd,   g_wt_d);

    cudaFuncSetAttribute(attn_f16_kernel,
                         cudaFuncAttributeMaxDynamicSharedMemorySize, ATT_SMEM);
    cudaFuncSetAttribute(gemm_f16_kernel<0>,
                         cudaFuncAttributeMaxDynamicSharedMemorySize, GEMM_SMEM);
    cudaFuncSetAttribute(gemm_f16_kernel<1>,
                         cudaFuncAttributeMaxDynamicSharedMemorySize, GEMM_SMEM);

    const dim3 blk(256);

    // ---- Fused conversions: one launch ----
    CvtArgs ca;
    ca.src[0] = sa_wq;  ca.dst[0] = wsaq;
    ca.src[1] = sa_wk;  ca.dst[1] = wsak;
    ca.src[2] = sa_wv;  ca.dst[2] = wsav;
    ca.src[3] = sa_wo;  ca.dst[3] = wsao;
    ca.src[4] = ca_wq;  ca.dst[4] = wcaq;
    ca.src[5] = ca_wk;  ca.dst[5] = wcak;
    ca.src[6] = ca_wv;  ca.dst[6] = wcav;
    ca.src[7] = ca_wo;  ca.dst[7] = wcao;
    ca.src[8] = w_gate; ca.dst[8] = wg;
    ca.src[9] = w_up;   ca.dst[9] = wu;
    ca.src[10] = w_down; ca.dst[10] = wd;
    ca.src[11] = context; ca.dst[11] = ctx16;
    fused_cvt_kernel<<<CVT_GRID, blk>>>(ca);

    const dim3 gH1(HDIM / 64, SQ / 128, 1);
    const dim3 gH2(HDIM / 64, SQ / 128, 2);
    const dim3 gH3(HDIM / 64, SQ / 128, 3);
    const dim3 gI2(ISZ / 64,  SQ / 128, 2);
    const dim3 gatt(SQ / 128, NH);

    // ---- Self-attention ----
    rmsnorm16_kernel<<<SQ, blk>>>(hidden, sa_norm, xn);
    gemm_f16_kernel<1><<<gH3, blk, GEMM_SMEM>>>(xn, wsaq, wsak, wsav, nullptr,
                                                q, k, v, SQ, HDIM, HDIM);
    attn_f16_kernel<<<gatt, blk, ATT_SMEM>>>(q, k, v, att);
    gemm_f16_kernel<0><<<gH1, blk, GEMM_SMEM>>>(att, wsao, wsao, wsao, hidden,
                                                h1, h1, h1, SQ, HDIM, HDIM);

    // ---- Cross-attention ----
    rmsnorm16_kernel<<<SQ, blk>>>(h1, ca_norm, xn);
    gemm_f16_kernel<1><<<gH1, blk, GEMM_SMEM>>>(xn, wcaq, wcaq, wcaq, nullptr,
                                                q, q, q, SQ, HDIM, HDIM);
    gemm_f16_kernel<1><<<gH2, blk, GEMM_SMEM>>>(ctx16, wcak, wcav, wcav,
                                                nullptr, k, v, v,
                                                SQ, HDIM, HDIM);
    attn_f16_kernel<<<gatt, blk, ATT_SMEM>>>(q, k, v, att);
    gemm_f16_kernel<0><<<gH1, blk, GEMM_SMEM>>>(att, wcao, wcao, wcao, h1,
                                                h2, h2, h2, SQ, HDIM, HDIM);

    // ---- MLP ----
    rmsnorm16_kernel<<<SQ, blk>>>(h2, mlp_norm, xn);
    gemm_f16_kernel<1><<<gI2, blk, GEMM_SMEM>>>(xn, wg, wu, wu, nullptr,
                                                gate, up, up, SQ, ISZ, HDIM);
    silu16_kernel<<<(SQ * ISZ / 2 + 255) / 256, blk>>>(gate, up, gu,
                                                       SQ * ISZ / 2);
    gemm_f16_kernel<0><<<gH1, blk, GEMM_SMEM>>>(gu, wd, wd, wd, h2,
                                                out, out, out, SQ, HDIM, ISZ);
}

// round 16
// speedup vs baseline: 1.4853x; 1.4853x over previous
#include <cuda_runtime.h>
#include <cuda_fp16.h>
#include <math.h>
#include <stdint.h>

// ---------------------------------------------------------------------------
// Problem dimensions
// ---------------------------------------------------------------------------
#define SQ   2048
#define HDIM 1024
#define NH   16
#define HD   64
#define ISZ  4096

// ---------------------------------------------------------------------------
// Scratch
// ---------------------------------------------------------------------------
__device__ __half g_xn [SQ * HDIM];
__device__ __half g_q  [SQ * HDIM];
__device__ __half g_k  [SQ * HDIM];
__device__ __half g_v  [SQ * HDIM];
__device__ __half g_att[SQ * HDIM];
__device__ __half g_ctx[SQ * HDIM];
__device__ float  g_h1 [SQ * HDIM];
__device__ float  g_h2 [SQ * HDIM];
__device__ __half g_gate[SQ * ISZ];
__device__ __half g_up  [SQ * ISZ];
__device__ __half g_gu  [SQ * ISZ];
// transposed fp16 weights [N][K]
__device__ __half g_wt_saq[HDIM * HDIM];
__device__ __half g_wt_sak[HDIM * HDIM];
__device__ __half g_wt_sav[HDIM * HDIM];
__device__ __half g_wt_sao[HDIM * HDIM];
__device__ __half g_wt_caq[HDIM * HDIM];
__device__ __half g_wt_cak[HDIM * HDIM];
__device__ __half g_wt_cav[HDIM * HDIM];
__device__ __half g_wt_cao[HDIM * HDIM];
__device__ __half g_wt_g  [ISZ * HDIM];
__device__ __half g_wt_u  [ISZ * HDIM];
__device__ __half g_wt_d  [HDIM * ISZ];

// ---------------------------------------------------------------------------
// Helpers
// ---------------------------------------------------------------------------
__device__ __forceinline__ void mma_f16(float* c, const uint32_t* a,
                                        uint32_t b0, uint32_t b1) {
    asm volatile(
        "mma.sync.aligned.m16n8k16.row.col.f32.f16.f16.f32 "
        "{%0,%1,%2,%3}, {%4,%5,%6,%7}, {%8,%9}, {%0,%1,%2,%3};"
        : "+f"(c[0]), "+f"(c[1]), "+f"(c[2]), "+f"(c[3])
        : "r"(a[0]), "r"(a[1]), "r"(a[2]), "r"(a[3]), "r"(b0), "r"(b1));
}

__device__ __forceinline__ void cp16(uint32_t smem_dst, const void* gsrc) {
    asm volatile("cp.async.ca.shared.global [%0], [%1], 16;\n"
                 :: "r"(smem_dst), "l"(gsrc));
}
__device__ __forceinline__ void cp_commit() {
    asm volatile("cp.async.commit_group;\n" ::: "memory");
}
template <int N>
__device__ __forceinline__ void cp_wait() {
    asm volatile("cp.async.wait_group %0;\n" :: "n"(N) : "memory");
}

__device__ __forceinline__ uint32_t h2u(half2 h) {
    return *reinterpret_cast<uint32_t*>(&h);
}

// ---------------------------------------------------------------------------
// Weight transpose + fp32->fp16
// ---------------------------------------------------------------------------
__global__ void __launch_bounds__(256) tr16_kernel(
    const float* __restrict__ in, __half* __restrict__ out, int K, int N)
{
    __shared__ float t[32][33];
    const int tx = threadIdx.x & 31;
    const int ty = threadIdx.x >> 5;
    const int n0 = blockIdx.x * 32;
    const int k0 = blockIdx.y * 32;
    #pragma unroll
    for (int j = 0; j < 4; ++j)
        t[ty + j * 8][tx] = in[(size_t)(k0 + ty + j * 8) * N + n0 + tx];
    __syncthreads();
    #pragma unroll
    for (int j = 0; j < 4; ++j)
        out[(size_t)(n0 + ty + j * 8) * K + k0 + tx] =
            __float2half_rn(t[tx][ty + j * 8]);
}

__global__ void __launch_bounds__(256) cvt16_kernel(
    const float* __restrict__ in, __half* __restrict__ out, int n4)
{
    const int i = blockIdx.x * blockDim.x + threadIdx.x;
    if (i >= n4) return;
    float4 v = ((const float4*)in)[i];
    ((half2*)out)[2 * i + 0] = __floats2half2_rn(v.x, v.y);
    ((half2*)out)[2 * i + 1] = __floats2half2_rn(v.z, v.w);
}

// ---------------------------------------------------------------------------
// RMSNorm: fp32 in -> fp16 out
// ---------------------------------------------------------------------------
__global__ void __launch_bounds__(256) rmsnorm16_kernel(
    const float* __restrict__ x, const float* __restrict__ w,
    __half* __restrict__ y)
{
    const int row = blockIdx.x;
    const int t   = threadIdx.x;
    float4 vx = ((const float4*)(x + (size_t)row * HDIM))[t];
    float s = vx.x*vx.x + vx.y*vx.y + vx.z*vx.z + vx.w*vx.w;
    #pragma unroll
    for (int o = 16; o; o >>= 1) s += __shfl_xor_sync(0xffffffffu, s, o);

    __shared__ float red[8];
    __shared__ float s_inv;
    if ((t & 31) == 0) red[t >> 5] = s;
    __syncthreads();
    if (t == 0) {
        float tot = 0.f;
        #pragma unroll
        for (int i = 0; i < 8; ++i) tot += red[i];
        s_inv = 1.0f / sqrtf(tot * (1.0f / (float)HDIM) + 1e-6f);
    }
    __syncthreads();
    const float r = s_inv;
    float4 vw = ((const float4*)w)[t];
    half2* yrow = (half2*)(y + (size_t)row * HDIM);
    yrow[2 * t + 0] = __floats2half2_rn(vx.x * r * vw.x, vx.y * r * vw.y);
    yrow[2 * t + 1] = __floats2half2_rn(vx.z * r * vw.z, vx.w * r * vw.w);
}

// ---------------------------------------------------------------------------
// fp16 mma.sync GEMM (m16n8k16), 3-stage cp.async pipeline (proven).
// ---------------------------------------------------------------------------
#define RS16  20
#define A16_STG (128 * RS16)
#define B16_STG (64 * RS16)
#define GEMM_SMEM ((3 * A16_STG + 3 * B16_STG) * 4)

template <int OUTF16>
__global__ void __launch_bounds__(256, 2) gemm_f16_kernel(
    const __half* __restrict__ A,
    const __half* __restrict__ B0, const __half* __restrict__ B1,
    const __half* __restrict__ B2,
    const float* __restrict__ R,
    void* __restrict__ C0, void* __restrict__ C1, void* __restrict__ C2,
    int M, int N, int K)
{
    extern __shared__ uint32_t smw[];
    uint32_t* As = smw;
    uint32_t* Bs = smw + 3 * A16_STG;

    const __half* B = (blockIdx.z == 0) ? B0 : (blockIdx.z == 1 ? B1 : B2);
    void*         C = (blockIdx.z == 0) ? C0 : (blockIdx.z == 1 ? C1 : C2);

    const int tid  = threadIdx.x;
    const int lane = tid & 31;
    const int wid  = tid >> 5;
    const int g    = lane >> 2;
    const int tig  = lane & 3;
    const int wm   = (wid >> 1) * 32;
    const int wn   = (wid & 1) * 32;
    const int bm   = blockIdx.y * 128;
    const int bn   = blockIdx.x * 64;

    float acc[2][4][4];
    #pragma unroll
    for (int mt = 0; mt < 2; ++mt)
        #pragma unroll
        for (int nt = 0; nt < 4; ++nt)
            #pragma unroll
            for (int e = 0; e < 4; ++e) acc[mt][nt][e] = 0.f;

    const int niter = K >> 5;

    auto issue = [&](int i, int s) {
        const int k0 = i << 5;
        #pragma unroll
        for (int it = 0; it < 2; ++it) {
            const int chunk = tid + it * 256;
            const int r = chunk >> 2;
            const int c = chunk & 3;
            uint32_t dst = (uint32_t)__cvta_generic_to_shared(
                &As[s * A16_STG + r * RS16 + 4 * c]);
            cp16(dst, A + (size_t)(bm + r) * K + k0 + 8 * c);
        }
        {
            const int r = tid >> 2;
            const int c = tid & 3;
            uint32_t dst = (uint32_t)__cvta_generic_to_shared(
                &Bs[s * B16_STG + r * RS16 + 4 * c]);
            cp16(dst, B + (size_t)(bn + r) * K + k0 + 8 * c);
        }
    };

    issue(0, 0);
    cp_commit();
    if (niter > 1) issue(1, 1);
    cp_commit();

    for (int i = 0; i < niter; ++i) {
        const int s = i - (i / 3) * 3;
        cp_wait<1>();
        __syncthreads();

        const uint32_t* Ast = As + s * A16_STG;
        const uint32_t* Bst = Bs + s * B16_STG;

        uint32_t af[2][2][4];
        uint32_t bf[2][4][2];
        #pragma unroll
        for (int kt = 0; kt < 2; ++kt) {
            #pragma unroll
            for (int nt = 0; nt < 4; ++nt) {
                const int base = (wn + nt * 8 + g) * RS16 + kt * 8 + tig;
                bf[kt][nt][0] = Bst[base];
                bf[kt][nt][1] = Bst[base + 4];
            }
            #pragma unroll
            for (int mt = 0; mt < 2; ++mt) {
                const int b0 = (wm + mt * 16 + g) * RS16 + kt * 8 + tig;
                af[kt][mt][0] = Ast[b0];
                af[kt][mt][1] = Ast[b0 + 8 * RS16];
                af[kt][mt][2] = Ast[b0 + 4];
                af[kt][mt][3] = Ast[b0 + 8 * RS16 + 4];
            }
        }

        #pragma unroll
        for (int kt = 0; kt < 2; ++kt)
            #pragma unroll
            for (int mt = 0; mt < 2; ++mt)
                #pragma unroll
                for (int nt = 0; nt < 4; ++nt)
                    mma_f16(acc[mt][nt], af[kt][mt],
                            bf[kt][nt][0], bf[kt][nt][1]);

        __syncthreads();
        const int j = i + 2;
        if (j < niter) issue(j, j - (j / 3) * 3);
        cp_commit();
    }

    #pragma unroll
    for (int mt = 0; mt < 2; ++mt) {
        const int r0 = bm + wm + mt * 16 + g;
        const int r1 = r0 + 8;
        #pragma unroll
        for (int nt = 0; nt < 4; ++nt) {
            const int col = bn + wn + nt * 8 + 2 * tig;
            if (OUTF16) {
                __half* Ch = (__half*)C;
                *(half2*)(Ch + (size_t)r0 * N + col) =
                    __floats2half2_rn(acc[mt][nt][0], acc[mt][nt][1]);
                *(half2*)(Ch + (size_t)r1 * N + col) =
                    __floats2half2_rn(acc[mt][nt][2], acc[mt][nt][3]);
            } else {
                float* Cf = (float*)C;
                float2 v0 = make_float2(acc[mt][nt][0], acc[mt][nt][1]);
                float2 v1 = make_float2(acc[mt][nt][2], acc[mt][nt][3]);
                if (R) {
                    float2 a0 = *(const float2*)(R + (size_t)r0 * N + col);
                    float2 a1 = *(const float2*)(R + (size_t)r1 * N + col);
                    v0.x += a0.x; v0.y += a0.y;
                    v1.x += a1.x; v1.y += a1.y;
                }
                *(float2*)(Cf + (size_t)r0 * N + col) = v0;
                *(float2*)(Cf + (size_t)r1 * N + col) = v1;
            }
        }
    }
}

// ---------------------------------------------------------------------------
// Flash attention, fp16 mma core (R13, proven).
// ---------------------------------------------------------------------------
#define AS16 36
#define ATT_SMEM ((128 * AS16 + 64 * AS16 + 64 * AS16) * 4)

__global__ void __launch_bounds__(256) attn_f16_kernel(
    const __half* __restrict__ Qg, const __half* __restrict__ Kg,
    const __half* __restrict__ Vg, __half* __restrict__ Og)
{
    extern __shared__ uint32_t sm[];
    uint32_t* Qs = sm;
    uint32_t* Ks = sm + 128 * AS16;
    uint32_t* Vt = sm + 192 * AS16;

    const int tid  = threadIdx.x;
    const int lane = tid & 31;
    const int wid  = tid >> 5;
    const int g    = lane >> 2;
    const int tig  = lane & 3;
    const int i0   = blockIdx.x * 128;
    const int hoff = blockIdx.y * HD;
    const int qrow = wid * 16;

    #pragma unroll
    for (int it = 0; it < 4; ++it) {
        const int chunk = tid + it * 256;
        const int r = chunk >> 3;
        const int c = chunk & 7;
        uint32_t dst = (uint32_t)__cvta_generic_to_shared(&Qs[r * AS16 + 4 * c]);
        cp16(dst, Qg + (size_t)(i0 + r) * HDIM + hoff + 8 * c);
    }
    cp_commit();

    float m0 = -1e30f, m1 = -1e30f;
    float l0 = 0.f, l1 = 0.f;
    float o[8][4];
    #pragma unroll
    for (int nt = 0; nt < 8; ++nt)
        #pragma unroll
        for (int e = 0; e < 4; ++e) o[nt][e] = 0.f;

    for (int j0 = 0; j0 < SQ; j0 += 64) {
        __syncthreads();
        #pragma unroll
        for (int it = 0; it < 2; ++it) {
            const int chunk = tid + it * 256;
            const int r = chunk >> 3;
            const int c = chunk & 7;
            uint32_t dst = (uint32_t)__cvta_generic_to_shared(
                &Ks[r * AS16 + 4 * c]);
            cp16(dst, Kg + (size_t)(j0 + r) * HDIM + hoff + 8 * c);
        }
        cp_commit();
        __half* Vth = (__half*)Vt;
        #pragma unroll
        for (int it = 0; it < 4; ++it) {
            const int r  = it * 16 + (tid >> 4);
            const int c4 = (tid & 15) << 2;
            const __half* vp = Vg + (size_t)(j0 + r) * HDIM + hoff + c4;
            half2 v0 = *(const half2*)(vp);
            half2 v1 = *(const half2*)(vp + 2);
            Vth[((c4 + 0) * AS16 + (r >> 1)) * 2 + (r & 1)] = __low2half(v0);
            Vth[((c4 + 1) * AS16 + (r >> 1)) * 2 + (r & 1)] = __high2half(v0);
            Vth[((c4 + 2) * AS16 + (r >> 1)) * 2 + (r & 1)] = __low2half(v1);
            Vth[((c4 + 3) * AS16 + (r >> 1)) * 2 + (r & 1)] = __high2half(v1);
        }
        cp_wait<0>();
        __syncthreads();

        float s[8][4];
        #pragma unroll
        for (int nt = 0; nt < 8; ++nt)
            #pragma unroll
            for (int e = 0; e < 4; ++e) s[nt][e] = 0.f;

        #pragma unroll
        for (int kt = 0; kt < 4; ++kt) {
            uint32_t a[4];
            const int base = (qrow + g) * AS16 + kt * 8 + tig;
            a[0] = Qs[base];
            a[1] = Qs[base + 8 * AS16];
            a[2] = Qs[base + 4];
            a[3] = Qs[base + 8 * AS16 + 4];
            #pragma unroll
            for (int nt = 0; nt < 8; ++nt) {
                const int jb = (nt * 8 + g) * AS16 + kt * 8 + tig;
                mma_f16(s[nt], a, Ks[jb], Ks[jb + 4]);
            }
        }
        #pragma unroll
        for (int nt = 0; nt < 8; ++nt)
            #pragma unroll
            for (int e = 0; e < 4; ++e) s[nt][e] *= 0.125f;

        float mt0 = -1e30f, mt1 = -1e30f;
        #pragma unroll
        for (int nt = 0; nt < 8; ++nt) {
            mt0 = fmaxf(mt0, fmaxf(s[nt][0], s[nt][1]));
            mt1 = fmaxf(mt1, fmaxf(s[nt][2], s[nt][3]));
        }
        mt0 = fmaxf(mt0, __shfl_xor_sync(0xffffffffu, mt0, 1));
        mt0 = fmaxf(mt0, __shfl_xor_sync(0xffffffffu, mt0, 2));
        mt1 = fmaxf(mt1, __shfl_xor_sync(0xffffffffu, mt1, 1));
        mt1 = fmaxf(mt1, __shfl_xor_sync(0xffffffffu, mt1, 2));

        const float mn0 = fmaxf(m0, mt0);
        const float mn1 = fmaxf(m1, mt1);
        const float c0 = __expf(m0 - mn0);
        const float c1 = __expf(m1 - mn1);
        m0 = mn0; m1 = mn1;

        float ps0 = 0.f, ps1 = 0.f;
        #pragma unroll
        for (int nt = 0; nt < 8; ++nt) {
            s[nt][0] = __expf(s[nt][0] - mn0);
            s[nt][1] = __expf(s[nt][1] - mn0);
            s[nt][2] = __expf(s[nt][2] - mn1);
            s[nt][3] = __expf(s[nt][3] - mn1);
            ps0 += s[nt][0] + s[nt][1];
            ps1 += s[nt][2] + s[nt][3];
        }
        ps0 += __shfl_xor_sync(0xffffffffu, ps0, 1);
        ps0 += __shfl_xor_sync(0xffffffffu, ps0, 2);
        ps1 += __shfl_xor_sync(0xffffffffu, ps1, 1);
        ps1 += __shfl_xor_sync(0xffffffffu, ps1, 2);
        l0 = l0 * c0 + ps0;
        l1 = l1 * c1 + ps1;

        #pragma unroll
        for (int nt = 0; nt < 8; ++nt) {
            o[nt][0] *= c0; o[nt][1] *= c0;
            o[nt][2] *= c1; o[nt][3] *= c1;
        }

        #pragma unroll
        for (int jt = 0; jt < 4; ++jt) {
            uint32_t a[4];
            a[0] = h2u(__floats2half2_rn(s[2 * jt][0],     s[2 * jt][1]));
            a[1] = h2u(__floats2half2_rn(s[2 * jt][2],     s[2 * jt][3]));
            a[2] = h2u(__floats2half2_rn(s[2 * jt + 1][0], s[2 * jt + 1][1]));
            a[3] = h2u(__floats2half2_rn(s[2 * jt + 1][2], s[2 * jt + 1][3]));
            #pragma unroll
            for (int nt = 0; nt < 8; ++nt) {
                const int vb = (nt * 8 + g) * AS16 + jt * 8 + tig;
                mma_f16(o[nt], a, Vt[vb], Vt[vb + 4]);
            }
        }
    }

    const float i0f = 1.0f / l0;
    const float i1f = 1.0f / l1;
    const int r0 = i0 + qrow + g;
    const int r1 = r0 + 8;
    #pragma unroll
    for (int nt = 0; nt < 8; ++nt) {
        const int col = hoff + nt * 8 + 2 * tig;
        *(half2*)(Og + (size_t)r0 * HDIM + col) =
            __floats2half2_rn(o[nt][0] * i0f, o[nt][1] * i0f);
        *(half2*)(Og + (size_t)r1 * HDIM + col) =
            __floats2half2_rn(o[nt][2] * i1f, o[nt][3] * i1f);
    }
}

// ---------------------------------------------------------------------------
// SwiGLU elementwise: fp16 in/out
// ---------------------------------------------------------------------------
__global__ void __launch_bounds__(256) silu16_kernel(
    const __half* __restrict__ g, const __half* __restrict__ u,
    __half* __restrict__ out, int n2)
{
    const int i = blockIdx.x * blockDim.x + threadIdx.x;
    if (i >= n2) return;
    float2 gf = __half22float2(((const half2*)g)[i]);
    float2 uf = __half22float2(((const half2*)u)[i]);
    float ox = gf.x * (1.0f / (1.0f + __expf(-gf.x))) * uf.x;
    float oy = gf.y * (1.0f / (1.0f + __expf(-gf.y))) * uf.y;
    ((half2*)out)[i] = __floats2half2_rn(ox, oy);
}

// ---------------------------------------------------------------------------
// Launch sequence
// ---------------------------------------------------------------------------
extern "C" void kernel_launch(void* const* d_in, const int* in_sizes, int n_in,
                              void* d_out, int out_size)
{
    (void)in_sizes; (void)n_in; (void)out_size;

    const float* hidden   = (const float*)d_in[0];
    const float* context  = (const float*)d_in[1];
    const float* sa_norm  = (const float*)d_in[2];
    const float* sa_wq    = (const float*)d_in[3];
    const float* sa_wk    = (const float*)d_in[4];
    const float* sa_wv    = (const float*)d_in[5];
    const float* sa_wo    = (const float*)d_in[6];
    const float* ca_norm  = (const float*)d_in[7];
    const float* ca_wq    = (const float*)d_in[8];
    const float* ca_wk    = (const float*)d_in[9];
    const float* ca_wv    = (const float*)d_in[10];
    const float* ca_wo    = (const float*)d_in[11];
    const float* mlp_norm = (const float*)d_in[12];
    const float* w_gate   = (const float*)d_in[13];
    const float* w_up     = (const float*)d_in[14];
    const float* w_down   = (const float*)d_in[15];
    float* out = (float*)d_out;

    __half *xn, *q, *k, *v, *att, *ctx16, *gate, *up, *gu;
    float *h1, *h2;
    cudaGetSymbolAddress((void**)&xn,    g_xn);
    cudaGetSymbolAddress((void**)&q,     g_q);
    cudaGetSymbolAddress((void**)&k,     g_k);
    cudaGetSymbolAddress((void**)&v,     g_v);
    cudaGetSymbolAddress((void**)&att,   g_att);
    cudaGetSymbolAddress((void**)&ctx16, g_ctx);
    cudaGetSymbolAddress((void**)&h1,    g_h1);
    cudaGetSymbolAddress((void**)&h2,    g_h2);
    cudaGetSymbolAddress((void**)&gate,  g_gate);
    cudaGetSymbolAddress((void**)&up,    g_up);
    cudaGetSymbolAddress((void**)&gu,    g_gu);

    __half *wsaq, *wsak, *wsav, *wsao, *wcaq, *wcak, *wcav, *wcao, *wg, *wu, *wd;
    cudaGetSymbolAddress((void**)&wsaq, g_wt_saq);
    cudaGetSymbolAddress((void**)&wsak, g_wt_sak);
    cudaGetSymbolAddress((void**)&wsav, g_wt_sav);
    cudaGetSymbolAddress((void**)&wsao, g_wt_sao);
    cudaGetSymbolAddress((void**)&wcaq, g_wt_caq);
    cudaGetSymbolAddress((void**)&wcak, g_wt_cak);
    cudaGetSymbolAddress((void**)&wcav, g_wt_cav);
    cudaGetSymbolAddress((void**)&wcao, g_wt_cao);
    cudaGetSymbolAddress((void**)&wg,   g_wt_g);
    cudaGetSymbolAddress((void**)&wu,   g_wt_u);
    cudaGetSymbolAddress((void**)&wd,   g_wt_d);

    cudaFuncSetAttribute(attn_f16_kernel,
                         cudaFuncAttributeMaxDynamicSharedMemorySize, ATT_SMEM);
    cudaFuncSetAttribute(gemm_f16_kernel<0>,
                         cudaFuncAttributeMaxDynamicSharedMemorySize, GEMM_SMEM);
    cudaFuncSetAttribute(gemm_f16_kernel<1>,
                         cudaFuncAttributeMaxDynamicSharedMemorySize, GEMM_SMEM);

    const dim3 blk(256);
    const dim3 tgH(HDIM / 32, HDIM / 32);

    // ---- Weight conversion (transpose + fp16) ----
    tr16_kernel<<<tgH, blk>>>(sa_wq, wsaq, HDIM, HDIM);
    tr16_kernel<<<tgH, blk>>>(sa_wk, wsak, HDIM, HDIM);
    tr16_kernel<<<tgH, blk>>>(sa_wv, wsav, HDIM, HDIM);
    tr16_kernel<<<tgH, blk>>>(sa_wo, wsao, HDIM, HDIM);
    tr16_kernel<<<tgH, blk>>>(ca_wq, wcaq, HDIM, HDIM);
    tr16_kernel<<<tgH, blk>>>(ca_wk, wcak, HDIM, HDIM);
    tr16_kernel<<<tgH, blk>>>(ca_wv, wcav, HDIM, HDIM);
    tr16_kernel<<<tgH, blk>>>(ca_wo, wcao, HDIM, HDIM);
    tr16_kernel<<<dim3(ISZ / 32, HDIM / 32), blk>>>(w_gate, wg, HDIM, ISZ);
    tr16_kernel<<<dim3(ISZ / 32, HDIM / 32), blk>>>(w_up,   wu, HDIM, ISZ);
    tr16_kernel<<<dim3(HDIM / 32, ISZ / 32), blk>>>(w_down, wd, ISZ, HDIM);
    cvt16_kernel<<<(SQ * HDIM / 4 + 255) / 256, blk>>>(context, ctx16,
                                                       SQ * HDIM / 4);

    const dim3 gH1(HDIM / 64, SQ / 128, 1);
    const dim3 gH2(HDIM / 64, SQ / 128, 2);
    const dim3 gH3(HDIM / 64, SQ / 128, 3);
    const dim3 gI2(ISZ / 64,  SQ / 128, 2);
    const dim3 gatt(SQ / 128, NH);

    // ---- Self-attention ----
    rmsnorm16_kernel<<<SQ, blk>>>(hidden, sa_norm, xn);
    gemm_f16_kernel<1><<<gH3, blk, GEMM_SMEM>>>(xn, wsaq, wsak, wsav, nullptr,
                                                q, k, v, SQ, HDIM, HDIM);
    attn_f16_kernel<<<gatt, blk, ATT_SMEM>>>(q, k, v, att);
    gemm_f16_kernel<0><<<gH1, blk, GEMM_SMEM>>>(att, wsao, wsao, wsao, hidden,
                                                h1, h1, h1, SQ, HDIM, HDIM);

    // ---- Cross-attention ----
    rmsnorm16_kernel<<<SQ, blk>>>(h1, ca_norm, xn);
    gemm_f16_kernel<1><<<gH1, blk, GEMM_SMEM>>>(xn, wcaq, wcaq, wcaq, nullptr,
                                                q, q, q, SQ, HDIM, HDIM);
    gemm_f16_kernel<1><<<gH2, blk, GEMM_SMEM>>>(ctx16, wcak, wcav, wcav,
                                                nullptr, k, v, v,
                                                SQ, HDIM, HDIM);
    attn_f16_kernel<<<gatt, blk, ATT_SMEM>>>(q, k, v, att);
    gemm_f16_kernel<0><<<gH1, blk, GEMM_SMEM>>>(att, wcao, wcao, wcao, h1,
                                                h2, h2, h2, SQ, HDIM, HDIM);

    // ---- MLP ----
    rmsnorm16_kernel<<<SQ, blk>>>(h2, mlp_norm, xn);
    gemm_f16_kernel<1><<<gI2, blk, GEMM_SMEM>>>(xn, wg, wu, wu, nullptr,
                                                gate, up, up, SQ, ISZ, HDIM);
    silu16_kernel<<<(SQ * ISZ / 2 + 255) / 256, blk>>>(gate, up, gu,
                                                       SQ * ISZ / 2);
    gemm_f16_kernel<0><<<gH1, blk, GEMM_SMEM>>>(gu, wd, wd, wd, h2,
                                                out, out, out, SQ, HDIM, ISZ);
}

// round 17
// speedup vs baseline: 1.5222x; 1.0249x over previous
#include <cuda_runtime.h>
#include <cuda_fp16.h>
#include <math.h>
#include <stdint.h>

// ---------------------------------------------------------------------------
// Problem dimensions
// ---------------------------------------------------------------------------
#define SQ   2048
#define HDIM 1024
#define NH   16
#define HD   64
#define ISZ  4096

// ---------------------------------------------------------------------------
// Scratch
// ---------------------------------------------------------------------------
__device__ __half g_xn [SQ * HDIM];
__device__ __half g_q  [SQ * HDIM];
__device__ __half g_k  [SQ * HDIM];
__device__ __half g_v  [SQ * HDIM];
__device__ __half g_att[SQ * HDIM];
__device__ __half g_ctx[SQ * HDIM];
__device__ float  g_h1 [SQ * HDIM];
__device__ float  g_h2 [SQ * HDIM];
__device__ __half g_gate[SQ * ISZ];
__device__ __half g_up  [SQ * ISZ];
__device__ __half g_gu  [SQ * ISZ];
// transposed fp16 weights [N][K]
__device__ __half g_wt_saq[HDIM * HDIM];
__device__ __half g_wt_sak[HDIM * HDIM];
__device__ __half g_wt_sav[HDIM * HDIM];
__device__ __half g_wt_sao[HDIM * HDIM];
__device__ __half g_wt_caq[HDIM * HDIM];
__device__ __half g_wt_cak[HDIM * HDIM];
__device__ __half g_wt_cav[HDIM * HDIM];
__device__ __half g_wt_cao[HDIM * HDIM];
__device__ __half g_wt_g  [ISZ * HDIM];
__device__ __half g_wt_u  [ISZ * HDIM];
__device__ __half g_wt_d  [HDIM * ISZ];

// ---------------------------------------------------------------------------
// Helpers
// ---------------------------------------------------------------------------
__device__ __forceinline__ void mma_f16(float* c, const uint32_t* a,
                                        uint32_t b0, uint32_t b1) {
    asm volatile(
        "mma.sync.aligned.m16n8k16.row.col.f32.f16.f16.f32 "
        "{%0,%1,%2,%3}, {%4,%5,%6,%7}, {%8,%9}, {%0,%1,%2,%3};"
        : "+f"(c[0]), "+f"(c[1]), "+f"(c[2]), "+f"(c[3])
        : "r"(a[0]), "r"(a[1]), "r"(a[2]), "r"(a[3]), "r"(b0), "r"(b1));
}

__device__ __forceinline__ void cp16(uint32_t smem_dst, const void* gsrc) {
    asm volatile("cp.async.ca.shared.global [%0], [%1], 16;\n"
                 :: "r"(smem_dst), "l"(gsrc));
}
__device__ __forceinline__ void cp_commit() {
    asm volatile("cp.async.commit_group;\n" ::: "memory");
}
template <int N>
__device__ __forceinline__ void cp_wait() {
    asm volatile("cp.async.wait_group %0;\n" :: "n"(N) : "memory");
}

__device__ __forceinline__ uint32_t h2u(half2 h) {
    return *reinterpret_cast<uint32_t*>(&h);
}

// ---------------------------------------------------------------------------
// Weight transpose + fp32->fp16 (proven)
// ---------------------------------------------------------------------------
__global__ void __launch_bounds__(256) tr16_kernel(
    const float* __restrict__ in, __half* __restrict__ out, int K, int N)
{
    __shared__ float t[32][33];
    const int tx = threadIdx.x & 31;
    const int ty = threadIdx.x >> 5;
    const int n0 = blockIdx.x * 32;
    const int k0 = blockIdx.y * 32;
    #pragma unroll
    for (int j = 0; j < 4; ++j)
        t[ty + j * 8][tx] = in[(size_t)(k0 + ty + j * 8) * N + n0 + tx];
    __syncthreads();
    #pragma unroll
    for (int j = 0; j < 4; ++j)
        out[(size_t)(n0 + ty + j * 8) * K + k0 + tx] =
            __float2half_rn(t[tx][ty + j * 8]);
}

__global__ void __launch_bounds__(256) cvt16_kernel(
    const float* __restrict__ in, __half* __restrict__ out, int n4)
{
    const int i = blockIdx.x * blockDim.x + threadIdx.x;
    if (i >= n4) return;
    float4 v = ((const float4*)in)[i];
    ((half2*)out)[2 * i + 0] = __floats2half2_rn(v.x, v.y);
    ((half2*)out)[2 * i + 1] = __floats2half2_rn(v.z, v.w);
}

// ---------------------------------------------------------------------------
// RMSNorm: fp32 in -> fp16 out (proven)
// ---------------------------------------------------------------------------
__global__ void __launch_bounds__(256) rmsnorm16_kernel(
    const float* __restrict__ x, const float* __restrict__ w,
    __half* __restrict__ y)
{
    const int row = blockIdx.x;
    const int t   = threadIdx.x;
    float4 vx = ((const float4*)(x + (size_t)row * HDIM))[t];
    float s = vx.x*vx.x + vx.y*vx.y + vx.z*vx.z + vx.w*vx.w;
    #pragma unroll
    for (int o = 16; o; o >>= 1) s += __shfl_xor_sync(0xffffffffu, s, o);

    __shared__ float red[8];
    __shared__ float s_inv;
    if ((t & 31) == 0) red[t >> 5] = s;
    __syncthreads();
    if (t == 0) {
        float tot = 0.f;
        #pragma unroll
        for (int i = 0; i < 8; ++i) tot += red[i];
        s_inv = 1.0f / sqrtf(tot * (1.0f / (float)HDIM) + 1e-6f);
    }
    __syncthreads();
    const float r = s_inv;
    float4 vw = ((const float4*)w)[t];
    half2* yrow = (half2*)(y + (size_t)row * HDIM);
    yrow[2 * t + 0] = __floats2half2_rn(vx.x * r * vw.x, vx.y * r * vw.y);
    yrow[2 * t + 1] = __floats2half2_rn(vx.z * r * vw.z, vx.w * r * vw.w);
}

// ---------------------------------------------------------------------------
// fp16 mma.sync GEMM (m16n8k16), 3-stage cp.async pipeline (proven).
// ---------------------------------------------------------------------------
#define RS16  20
#define A16_STG (128 * RS16)
#define B16_STG (64 * RS16)
#define GEMM_SMEM ((3 * A16_STG + 3 * B16_STG) * 4)

template <int OUTF16>
__global__ void __launch_bounds__(256, 2) gemm_f16_kernel(
    const __half* __restrict__ A,
    const __half* __restrict__ B0, const __half* __restrict__ B1,
    const __half* __restrict__ B2,
    const float* __restrict__ R,
    void* __restrict__ C0, void* __restrict__ C1, void* __restrict__ C2,
    int M, int N, int K)
{
    extern __shared__ uint32_t smw[];
    uint32_t* As = smw;
    uint32_t* Bs = smw + 3 * A16_STG;

    const __half* B = (blockIdx.z == 0) ? B0 : (blockIdx.z == 1 ? B1 : B2);
    void*         C = (blockIdx.z == 0) ? C0 : (blockIdx.z == 1 ? C1 : C2);

    const int tid  = threadIdx.x;
    const int lane = tid & 31;
    const int wid  = tid >> 5;
    const int g    = lane >> 2;
    const int tig  = lane & 3;
    const int wm   = (wid >> 1) * 32;
    const int wn   = (wid & 1) * 32;
    const int bm   = blockIdx.y * 128;
    const int bn   = blockIdx.x * 64;

    float acc[2][4][4];
    #pragma unroll
    for (int mt = 0; mt < 2; ++mt)
        #pragma unroll
        for (int nt = 0; nt < 4; ++nt)
            #pragma unroll
            for (int e = 0; e < 4; ++e) acc[mt][nt][e] = 0.f;

    const int niter = K >> 5;

    auto issue = [&](int i, int s) {
        const int k0 = i << 5;
        #pragma unroll
        for (int it = 0; it < 2; ++it) {
            const int chunk = tid + it * 256;
            const int r = chunk >> 2;
            const int c = chunk & 3;
            uint32_t dst = (uint32_t)__cvta_generic_to_shared(
                &As[s * A16_STG + r * RS16 + 4 * c]);
            cp16(dst, A + (size_t)(bm + r) * K + k0 + 8 * c);
        }
        {
            const int r = tid >> 2;
            const int c = tid & 3;
            uint32_t dst = (uint32_t)__cvta_generic_to_shared(
                &Bs[s * B16_STG + r * RS16 + 4 * c]);
            cp16(dst, B + (size_t)(bn + r) * K + k0 + 8 * c);
        }
    };

    issue(0, 0);
    cp_commit();
    if (niter > 1) issue(1, 1);
    cp_commit();

    for (int i = 0; i < niter; ++i) {
        const int s = i - (i / 3) * 3;
        cp_wait<1>();
        __syncthreads();

        const uint32_t* Ast = As + s * A16_STG;
        const uint32_t* Bst = Bs + s * B16_STG;

        uint32_t af[2][2][4];
        uint32_t bf[2][4][2];
        #pragma unroll
        for (int kt = 0; kt < 2; ++kt) {
            #pragma unroll
            for (int nt = 0; nt < 4; ++nt) {
                const int base = (wn + nt * 8 + g) * RS16 + kt * 8 + tig;
                bf[kt][nt][0] = Bst[base];
                bf[kt][nt][1] = Bst[base + 4];
            }
            #pragma unroll
            for (int mt = 0; mt < 2; ++mt) {
                const int b0 = (wm + mt * 16 + g) * RS16 + kt * 8 + tig;
                af[kt][mt][0] = Ast[b0];
                af[kt][mt][1] = Ast[b0 + 8 * RS16];
                af[kt][mt][2] = Ast[b0 + 4];
                af[kt][mt][3] = Ast[b0 + 8 * RS16 + 4];
            }
        }

        #pragma unroll
        for (int kt = 0; kt < 2; ++kt)
            #pragma unroll
            for (int mt = 0; mt < 2; ++mt)
                #pragma unroll
                for (int nt = 0; nt < 4; ++nt)
                    mma_f16(acc[mt][nt], af[kt][mt],
                            bf[kt][nt][0], bf[kt][nt][1]);

        __syncthreads();
        const int j = i + 2;
        if (j < niter) issue(j, j - (j / 3) * 3);
        cp_commit();
    }

    #pragma unroll
    for (int mt = 0; mt < 2; ++mt) {
        const int r0 = bm + wm + mt * 16 + g;
        const int r1 = r0 + 8;
        #pragma unroll
        for (int nt = 0; nt < 4; ++nt) {
            const int col = bn + wn + nt * 8 + 2 * tig;
            if (OUTF16) {
                __half* Ch = (__half*)C;
                *(half2*)(Ch + (size_t)r0 * N + col) =
                    __floats2half2_rn(acc[mt][nt][0], acc[mt][nt][1]);
                *(half2*)(Ch + (size_t)r1 * N + col) =
                    __floats2half2_rn(acc[mt][nt][2], acc[mt][nt][3]);
            } else {
                float* Cf = (float*)C;
                float2 v0 = make_float2(acc[mt][nt][0], acc[mt][nt][1]);
                float2 v1 = make_float2(acc[mt][nt][2], acc[mt][nt][3]);
                if (R) {
                    float2 a0 = *(const float2*)(R + (size_t)r0 * N + col);
                    float2 a1 = *(const float2*)(R + (size_t)r1 * N + col);
                    v0.x += a0.x; v0.y += a0.y;
                    v1.x += a1.x; v1.y += a1.y;
                }
                *(float2*)(Cf + (size_t)r0 * N + col) = v0;
                *(float2*)(Cf + (size_t)r1 * N + col) = v1;
            }
        }
    }
}

// ---------------------------------------------------------------------------
// Flash attention, fp16 mma core, PIPELINED:
// K double-buffered via cp.async (1 tile ahead); V prefetched 1 tile ahead
// into registers, committed to single-buffered Vt at top of next iteration.
// ---------------------------------------------------------------------------
#define AS16 36
// Qs[128][36] + Ks[2][64][36] + Vt[64][36]
#define ATT_SMEM ((128 * AS16 + 2 * 64 * AS16 + 64 * AS16) * 4)

__global__ void __launch_bounds__(256) attn_f16_kernel(
    const __half* __restrict__ Qg, const __half* __restrict__ Kg,
    const __half* __restrict__ Vg, __half* __restrict__ Og)
{
    extern __shared__ uint32_t sm[];
    uint32_t* Qs = sm;                             // [128][36]
    uint32_t* Ks = sm + 128 * AS16;                // [2][64][36]
    uint32_t* Vt = sm + 128 * AS16 + 2 * 64 * AS16; // [64][36]

    const int tid  = threadIdx.x;
    const int lane = tid & 31;
    const int wid  = tid >> 5;
    const int g    = lane >> 2;
    const int tig  = lane & 3;
    const int i0   = blockIdx.x * 128;
    const int hoff = blockIdx.y * HD;
    const int qrow = wid * 16;

    // K tile issue into stage st
    auto kissue = [&](int j0, int st) {
        #pragma unroll
        for (int it = 0; it < 2; ++it) {
            const int chunk = tid + it * 256;
            const int r = chunk >> 3;
            const int c = chunk & 7;
            uint32_t dst = (uint32_t)__cvta_generic_to_shared(
                &Ks[st * 64 * AS16 + r * AS16 + 4 * c]);
            cp16(dst, Kg + (size_t)(j0 + r) * HDIM + hoff + 8 * c);
        }
    };

    // Prologue: Q + K0 cp.async (group G0), V0 into registers
    #pragma unroll
    for (int it = 0; it < 4; ++it) {
        const int chunk = tid + it * 256;
        const int r = chunk >> 3;
        const int c = chunk & 7;
        uint32_t dst = (uint32_t)__cvta_generic_to_shared(&Qs[r * AS16 + 4 * c]);
        cp16(dst, Qg + (size_t)(i0 + r) * HDIM + hoff + 8 * c);
    }
    kissue(0, 0);
    cp_commit();   // G0

    const int vr_r  = tid >> 4;          // base row within 16-row group
    const int vr_c4 = (tid & 15) << 2;   // d base
    half2 vr[8];
    #pragma unroll
    for (int it = 0; it < 4; ++it) {
        const __half* vp = Vg + (size_t)(it * 16 + vr_r) * HDIM + hoff + vr_c4;
        vr[2 * it + 0] = *(const half2*)(vp);
        vr[2 * it + 1] = *(const half2*)(vp + 2);
    }

    float m0 = -1e30f, m1 = -1e30f;
    float l0 = 0.f, l1 = 0.f;
    float o[8][4];
    #pragma unroll
    for (int nt = 0; nt < 8; ++nt)
        #pragma unroll
        for (int e = 0; e < 4; ++e) o[nt][e] = 0.f;

    for (int jt = 0; jt < SQ / 64; ++jt) {
        const int s = jt & 1;

        // Commit V regs (tile jt) to Vt; prior iteration's PV has consumed Vt.
        __syncthreads();
        {
            __half* Vth = (__half*)Vt;
            #pragma unroll
            for (int it = 0; it < 4; ++it) {
                const int r = it * 16 + vr_r;
                half2 v0 = vr[2 * it + 0];
                half2 v1 = vr[2 * it + 1];
                Vth[((vr_c4 + 0) * AS16 + (r >> 1)) * 2 + (r & 1)] = __low2half(v0);
                Vth[((vr_c4 + 1) * AS16 + (r >> 1)) * 2 + (r & 1)] = __high2half(v0);
                Vth[((vr_c4 + 2) * AS16 + (r >> 1)) * 2 + (r & 1)] = __low2half(v1);
                Vth[((vr_c4 + 3) * AS16 + (r >> 1)) * 2 + (r & 1)] = __high2half(v1);
            }
        }

        // Prefetch next tile: K via cp.async (stage s^1), V into registers
        if (jt + 1 < SQ / 64) {
            const int j0n = (jt + 1) * 64;
            kissue(j0n, s ^ 1);
            #pragma unroll
            for (int it = 0; it < 4; ++it) {
                const __half* vp =
                    Vg + (size_t)(j0n + it * 16 + vr_r) * HDIM + hoff + vr_c4;
                vr[2 * it + 0] = *(const half2*)(vp);
                vr[2 * it + 1] = *(const half2*)(vp + 2);
            }
        }
        cp_commit();       // unconditional (empty in tail) -> G(jt+1)
        cp_wait<1>();      // G(jt) done -> K tile jt resident (and Q on jt=0)
        __syncthreads();

        const uint32_t* Kst = Ks + s * 64 * AS16;

        // ---- S = Q K^T ----
        float sx[8][4];
        #pragma unroll
        for (int nt = 0; nt < 8; ++nt)
            #pragma unroll
            for (int e = 0; e < 4; ++e) sx[nt][e] = 0.f;

        #pragma unroll
        for (int kt = 0; kt < 4; ++kt) {
            uint32_t a[4];
            const int base = (qrow + g) * AS16 + kt * 8 + tig;
            a[0] = Qs[base];
            a[1] = Qs[base + 8 * AS16];
            a[2] = Qs[base + 4];
            a[3] = Qs[base + 8 * AS16 + 4];
            #pragma unroll
            for (int nt = 0; nt < 8; ++nt) {
                const int jb = (nt * 8 + g) * AS16 + kt * 8 + tig;
                mma_f16(sx[nt], a, Kst[jb], Kst[jb + 4]);
            }
        }
        #pragma unroll
        for (int nt = 0; nt < 8; ++nt)
            #pragma unroll
            for (int e = 0; e < 4; ++e) sx[nt][e] *= 0.125f;

        // ---- Online softmax ----
        float mt0 = -1e30f, mt1 = -1e30f;
        #pragma unroll
        for (int nt = 0; nt < 8; ++nt) {
            mt0 = fmaxf(mt0, fmaxf(sx[nt][0], sx[nt][1]));
            mt1 = fmaxf(mt1, fmaxf(sx[nt][2], sx[nt][3]));
        }
        mt0 = fmaxf(mt0, __shfl_xor_sync(0xffffffffu, mt0, 1));
        mt0 = fmaxf(mt0, __shfl_xor_sync(0xffffffffu, mt0, 2));
        mt1 = fmaxf(mt1, __shfl_xor_sync(0xffffffffu, mt1, 1));
        mt1 = fmaxf(mt1, __shfl_xor_sync(0xffffffffu, mt1, 2));

        const float mn0 = fmaxf(m0, mt0);
        const float mn1 = fmaxf(m1, mt1);
        const float c0 = __expf(m0 - mn0);
        const float c1 = __expf(m1 - mn1);
        m0 = mn0; m1 = mn1;

        float ps0 = 0.f, ps1 = 0.f;
        #pragma unroll
        for (int nt = 0; nt < 8; ++nt) {
            sx[nt][0] = __expf(sx[nt][0] - mn0);
            sx[nt][1] = __expf(sx[nt][1] - mn0);
            sx[nt][2] = __expf(sx[nt][2] - mn1);
            sx[nt][3] = __expf(sx[nt][3] - mn1);
            ps0 += sx[nt][0] + sx[nt][1];
            ps1 += sx[nt][2] + sx[nt][3];
        }
        ps0 += __shfl_xor_sync(0xffffffffu, ps0, 1);
        ps0 += __shfl_xor_sync(0xffffffffu, ps0, 2);
        ps1 += __shfl_xor_sync(0xffffffffu, ps1, 1);
        ps1 += __shfl_xor_sync(0xffffffffu, ps1, 2);
        l0 = l0 * c0 + ps0;
        l1 = l1 * c1 + ps1;

        #pragma unroll
        for (int nt = 0; nt < 8; ++nt) {
            o[nt][0] *= c0; o[nt][1] *= c0;
            o[nt][2] *= c1; o[nt][3] *= c1;
        }

        // ---- O += P V (C-fragment -> A-fragment identity) ----
        #pragma unroll
        for (int pj = 0; pj < 4; ++pj) {
            uint32_t a[4];
            a[0] = h2u(__floats2half2_rn(sx[2 * pj][0],     sx[2 * pj][1]));
            a[1] = h2u(__floats2half2_rn(sx[2 * pj][2],     sx[2 * pj][3]));
            a[2] = h2u(__floats2half2_rn(sx[2 * pj + 1][0], sx[2 * pj + 1][1]));
            a[3] = h2u(__floats2half2_rn(sx[2 * pj + 1][2], sx[2 * pj + 1][3]));
            #pragma unroll
            for (int nt = 0; nt < 8; ++nt) {
                const int vb = (nt * 8 + g) * AS16 + pj * 8 + tig;
                mma_f16(o[nt], a, Vt[vb], Vt[vb + 4]);
            }
        }
    }

    const float i0f = 1.0f / l0;
    const float i1f = 1.0f / l1;
    const int r0 = i0 + qrow + g;
    const int r1 = r0 + 8;
    #pragma unroll
    for (int nt = 0; nt < 8; ++nt) {
        const int col = hoff + nt * 8 + 2 * tig;
        *(half2*)(Og + (size_t)r0 * HDIM + col) =
            __floats2half2_rn(o[nt][0] * i0f, o[nt][1] * i0f);
        *(half2*)(Og + (size_t)r1 * HDIM + col) =
            __floats2half2_rn(o[nt][2] * i1f, o[nt][3] * i1f);
    }
}

// ---------------------------------------------------------------------------
// SwiGLU elementwise: fp16 in/out (proven)
// ---------------------------------------------------------------------------
__global__ void __launch_bounds__(256) silu16_kernel(
    const __half* __restrict__ g, const __half* __restrict__ u,
    __half* __restrict__ out, int n2)
{
    const int i = blockIdx.x * blockDim.x + threadIdx.x;
    if (i >= n2) return;
    float2 gf = __half22float2(((const half2*)g)[i]);
    float2 uf = __half22float2(((const half2*)u)[i]);
    float ox = gf.x * (1.0f / (1.0f + __expf(-gf.x))) * uf.x;
    float oy = gf.y * (1.0f / (1.0f + __expf(-gf.y))) * uf.y;
    ((half2*)out)[i] = __floats2half2_rn(ox, oy);
}

// ---------------------------------------------------------------------------
// Launch sequence
// ---------------------------------------------------------------------------
extern "C" void kernel_launch(void* const* d_in, const int* in_sizes, int n_in,
                              void* d_out, int out_size)
{
    (void)in_sizes; (void)n_in; (void)out_size;

    const float* hidden   = (const float*)d_in[0];
    const float* context  = (const float*)d_in[1];
    const float* sa_norm  = (const float*)d_in[2];
    const float* sa_wq    = (const float*)d_in[3];
    const float* sa_wk    = (const float*)d_in[4];
    const float* sa_wv    = (const float*)d_in[5];
    const float* sa_wo    = (const float*)d_in[6];
    const float* ca_norm  = (const float*)d_in[7];
    const float* ca_wq    = (const float*)d_in[8];
    const float* ca_wk    = (const float*)d_in[9];
    const float* ca_wv    = (const float*)d_in[10];
    const float* ca_wo    = (const float*)d_in[11];
    const float* mlp_norm = (const float*)d_in[12];
    const float* w_gate   = (const float*)d_in[13];
    const float* w_up     = (const float*)d_in[14];
    const float* w_down   = (const float*)d_in[15];
    float* out = (float*)d_out;

    __half *xn, *q, *k, *v, *att, *ctx16, *gate, *up, *gu;
    float *h1, *h2;
    cudaGetSymbolAddress((void**)&xn,    g_xn);
    cudaGetSymbolAddress((void**)&q,     g_q);
    cudaGetSymbolAddress((void**)&k,     g_k);
    cudaGetSymbolAddress((void**)&v,     g_v);
    cudaGetSymbolAddress((void**)&att,   g_att);
    cudaGetSymbolAddress((void**)&ctx16, g_ctx);
    cudaGetSymbolAddress((void**)&h1,    g_h1);
    cudaGetSymbolAddress((void**)&h2,    g_h2);
    cudaGetSymbolAddress((void**)&gate,  g_gate);
    cudaGetSymbolAddress((void**)&up,    g_up);
    cudaGetSymbolAddress((void**)&gu,    g_gu);

    __half *wsaq, *wsak, *wsav, *wsao, *wcaq, *wcak, *wcav, *wcao, *wg, *wu, *wd;
    cudaGetSymbolAddress((void**)&wsaq, g_wt_saq);
    cudaGetSymbolAddress((void**)&wsak, g_wt_sak);
    cudaGetSymbolAddress((void**)&wsav, g_wt_sav);
    cudaGetSymbolAddress((void**)&wsao, g_wt_sao);
    cudaGetSymbolAddress((void**)&wcaq, g_wt_caq);
    cudaGetSymbolAddress((void**)&wcak, g_wt_cak);
    cudaGetSymbolAddress((void**)&wcav, g_wt_cav);
    cudaGetSymbolAddress((void**)&wcao, g_wt_cao);
    cudaGetSymbolAddress((void**)&wg,   g_wt_g);
    cudaGetSymbolAddress((void**)&wu,   g_wt_u);
    cudaGetSymbolAddress((void**)&wd,   g_wt_d);

    cudaFuncSetAttribute(attn_f16_kernel,
                         cudaFuncAttributeMaxDynamicSharedMemorySize, ATT_SMEM);
    cudaFuncSetAttribute(gemm_f16_kernel<0>,
                         cudaFuncAttributeMaxDynamicSharedMemorySize, GEMM_SMEM);
    cudaFuncSetAttribute(gemm_f16_kernel<1>,
                         cudaFuncAttributeMaxDynamicSharedMemorySize, GEMM_SMEM);

    const dim3 blk(256);
    const dim3 tgH(HDIM / 32, HDIM / 32);

    // ---- Weight conversion (transpose + fp16): 12 proven small launches ----
    tr16_kernel<<<tgH, blk>>>(sa_wq, wsaq, HDIM, HDIM);
    tr16_kernel<<<tgH, blk>>>(sa_wk, wsak, HDIM, HDIM);
    tr16_kernel<<<tgH, blk>>>(sa_wv, wsav, HDIM, HDIM);
    tr16_kernel<<<tgH, blk>>>(sa_wo, wsao, HDIM, HDIM);
    tr16_kernel<<<tgH, blk>>>(ca_wq, wcaq, HDIM, HDIM);
    tr16_kernel<<<tgH, blk>>>(ca_wk, wcak, HDIM, HDIM);
    tr16_kernel<<<tgH, blk>>>(ca_wv, wcav, HDIM, HDIM);
    tr16_kernel<<<tgH, blk>>>(ca_wo, wcao, HDIM, HDIM);
    tr16_kernel<<<dim3(ISZ / 32, HDIM / 32), blk>>>(w_gate, wg, HDIM, ISZ);
    tr16_kernel<<<dim3(ISZ / 32, HDIM / 32), blk>>>(w_up,   wu, HDIM, ISZ);
    tr16_kernel<<<dim3(HDIM / 32, ISZ / 32), blk>>>(w_down, wd, ISZ, HDIM);
    cvt16_kernel<<<(SQ * HDIM / 4 + 255) / 256, blk>>>(context, ctx16,
                                                       SQ * HDIM / 4);

    const dim3 gH1(HDIM / 64, SQ / 128, 1);
    const dim3 gH2(HDIM / 64, SQ / 128, 2);
    const dim3 gH3(HDIM / 64, SQ / 128, 3);
    const dim3 gI2(ISZ / 64,  SQ / 128, 2);
    const dim3 gatt(SQ / 128, NH);

    // ---- Self-attention ----
    rmsnorm16_kernel<<<SQ, blk>>>(hidden, sa_norm, xn);
    gemm_f16_kernel<1><<<gH3, blk, GEMM_SMEM>>>(xn, wsaq, wsak, wsav, nullptr,
                                                q, k, v, SQ, HDIM, HDIM);
    attn_f16_kernel<<<gatt, blk, ATT_SMEM>>>(q, k, v, att);
    gemm_f16_kernel<0><<<gH1, blk, GEMM_SMEM>>>(att, wsao, wsao, wsao, hidden,
                                                h1, h1, h1, SQ, HDIM, HDIM);

    // ---- Cross-attention ----
    rmsnorm16_kernel<<<SQ, blk>>>(h1, ca_norm, xn);
    gemm_f16_kernel<1><<<gH1, blk, GEMM_SMEM>>>(xn, wcaq, wcaq, wcaq, nullptr,
                                                q, q, q, SQ, HDIM, HDIM);
    gemm_f16_kernel<1><<<gH2, blk, GEMM_SMEM>>>(ctx16, wcak, wcav, wcav,
                                                nullptr, k, v, v,
                                                SQ, HDIM, HDIM);
    attn_f16_kernel<<<gatt, blk, ATT_SMEM>>>(q, k, v, att);
    gemm_f16_kernel<0><<<gH1, blk, GEMM_SMEM>>>(att, wcao, wcao, wcao, h1,
                                                h2, h2, h2, SQ, HDIM, HDIM);

    // ---- MLP ----
    rmsnorm16_kernel<<<SQ, blk>>>(h2, mlp_norm, xn);
    gemm_f16_kernel<1><<<gI2, blk, GEMM_SMEM>>>(xn, wg, wu, wu, nullptr,
                                                gate, up, up, SQ, ISZ, HDIM);
    silu16_kernel<<<(SQ * ISZ / 2 + 255) / 256, blk>>>(gate, up, gu,
                                                       SQ * ISZ / 2);
    gemm_f16_kernel<0><<<gH1, blk, GEMM_SMEM>>>(gu, wd, wd, wd, h2,
                                                out, out, out, SQ, HDIM, ISZ);
}